// round 1
// baseline (speedup 1.0000x reference)
#include <cuda_runtime.h>
#include <cuda_bf16.h>

// DinoPool: block-diagonal masked attention with score_mod == const
// => masked average pooling of V over 512-row blocks.
// x: [B=4, S=4096, H*D=384] fp32. out: same shape.
// out[b, s, c] = mean over rows r in block(s) of x[b, r, c]; block size 512.
//
// Grid: (col_chunk=3, block=8, batch=4). 256 threads.
// Each CTA: sums 512 rows x 32 float4 (128 floats), then broadcasts mean
// to 512 output rows. All HBM traffic is the mandatory 2x25.2MB.

static constexpr int S        = 4096;
static constexpr int C        = 384;    // H*D
static constexpr int C4       = C / 4;  // 96 float4 per row
static constexpr int BLOCK    = 512;
static constexpr int CHUNK4   = 32;     // float4 columns per CTA
static constexpr int NTHREADS = 256;
static constexpr int ROWGRPS  = NTHREADS / CHUNK4;          // 8
static constexpr int ROWS_PER_THREAD = BLOCK / ROWGRPS;     // 64

__global__ __launch_bounds__(NTHREADS, 1)
void dinopool_kernel(const float* __restrict__ x, float* __restrict__ out) {
    const int chunk = blockIdx.x;   // 0..2
    const int blk   = blockIdx.y;   // 0..7
    const int bat   = blockIdx.z;   // 0..3

    const int c  = threadIdx.x & (CHUNK4 - 1);   // float4 column within chunk
    const int rg = threadIdx.x >> 5;             // row group 0..7

    const float4* __restrict__ x4 = reinterpret_cast<const float4*>(x);
    float4* __restrict__ o4       = reinterpret_cast<float4*>(out);

    // base index (in float4 units) of row 0 of this (batch, block), this column
    const size_t base = ((size_t)bat * S + (size_t)blk * BLOCK) * C4
                        + (size_t)chunk * CHUNK4 + c;

    // ---- accumulate 64 rows per thread ----
    float4 acc = make_float4(0.f, 0.f, 0.f, 0.f);
    size_t p = base + (size_t)rg * ROWS_PER_THREAD * C4;
    #pragma unroll 8
    for (int r = 0; r < ROWS_PER_THREAD; r++) {
        float4 v = __ldg(&x4[p]);
        p += C4;
        acc.x += v.x; acc.y += v.y; acc.z += v.z; acc.w += v.w;
    }

    // ---- cross-rowgroup reduction in smem ----
    __shared__ float4 smem[ROWGRPS][CHUNK4];
    smem[rg][c] = acc;
    __syncthreads();

    if (threadIdx.x < CHUNK4) {
        float4 t = smem[0][c];
        #pragma unroll
        for (int i = 1; i < ROWGRPS; i++) {
            float4 v = smem[i][c];
            t.x += v.x; t.y += v.y; t.z += v.z; t.w += v.w;
        }
        const float inv = 1.0f / (float)BLOCK;
        t.x *= inv; t.y *= inv; t.z *= inv; t.w *= inv;
        smem[0][c] = t;
    }
    __syncthreads();

    // ---- broadcast the mean to all 512 rows of the output block ----
    const float4 mean = smem[0][c];
    size_t op = base + (size_t)rg * C4;
    #pragma unroll 8
    for (int i = 0; i < ROWS_PER_THREAD; i++) {
        o4[op] = mean;
        op += (size_t)ROWGRPS * C4;
    }
}

extern "C" void kernel_launch(void* const* d_in, const int* in_sizes, int n_in,
                              void* d_out, int out_size) {
    const float* x = (const float*)d_in[0];   // [4, 4096, 384] fp32
    float* out     = (float*)d_out;           // [4, 4096, 384] fp32
    (void)in_sizes; (void)n_in; (void)out_size;

    dim3 grid(C4 / CHUNK4 /*3*/, S / BLOCK /*8*/, 4 /*batch*/);
    dinopool_kernel<<<grid, NTHREADS>>>(x, out);
}

// round 2
// speedup vs baseline: 1.0489x; 1.0489x over previous
#include <cuda_runtime.h>
#include <cuda_bf16.h>

// DinoPool == masked average pooling of x over 512-row blocks.
// x: [B=4, S=4096, C=384] fp32 -> out same shape.
// out[b, s, c] = mean_{r in block(s)} x[b, r, c].
//
// R2: 96 CTAs x 1024 threads (was 256). 32 warps/SM on busy SMs -> 4x
// memory-level parallelism to cover DRAM latency. Layout unchanged:
// each warp reads/writes one contiguous 512B row segment.

static constexpr int S        = 4096;
static constexpr int C        = 384;    // H*D
static constexpr int C4       = C / 4;  // 96 float4 per row
static constexpr int BLOCK    = 512;
static constexpr int CHUNK4   = 32;     // float4 columns per CTA
static constexpr int NTHREADS = 1024;
static constexpr int ROWGRPS  = NTHREADS / CHUNK4;          // 32
static constexpr int ROWS_PER_THREAD = BLOCK / ROWGRPS;     // 16

__global__ __launch_bounds__(NTHREADS, 1)
void dinopool_kernel(const float* __restrict__ x, float* __restrict__ out) {
    const int chunk = blockIdx.x;   // 0..2
    const int blk   = blockIdx.y;   // 0..7
    const int bat   = blockIdx.z;   // 0..3

    const int c  = threadIdx.x & (CHUNK4 - 1);   // float4 column within chunk
    const int rg = threadIdx.x >> 5;             // row group 0..31

    const float4* __restrict__ x4 = reinterpret_cast<const float4*>(x);
    float4* __restrict__ o4       = reinterpret_cast<float4*>(out);

    // base index (in float4 units) of row 0 of this (batch, block), this column
    const size_t base = ((size_t)bat * S + (size_t)blk * BLOCK) * C4
                        + (size_t)chunk * CHUNK4 + c;

    // ---- accumulate 16 rows per thread (independent loads, high MLP) ----
    float4 acc = make_float4(0.f, 0.f, 0.f, 0.f);
    size_t p = base + (size_t)rg * ROWS_PER_THREAD * C4;
    #pragma unroll
    for (int r = 0; r < ROWS_PER_THREAD; r++) {
        float4 v = __ldg(&x4[p + (size_t)r * C4]);
        acc.x += v.x; acc.y += v.y; acc.z += v.z; acc.w += v.w;
    }

    // ---- cross-rowgroup reduction in smem ----
    __shared__ float4 smem[ROWGRPS][CHUNK4];
    smem[rg][c] = acc;
    __syncthreads();

    if (threadIdx.x < CHUNK4) {
        float4 t = smem[0][c];
        #pragma unroll
        for (int i = 1; i < ROWGRPS; i++) {
            float4 v = smem[i][c];
            t.x += v.x; t.y += v.y; t.z += v.z; t.w += v.w;
        }
        const float inv = 1.0f / (float)BLOCK;
        t.x *= inv; t.y *= inv; t.z *= inv; t.w *= inv;
        smem[0][c] = t;
    }
    __syncthreads();

    // ---- broadcast the mean to all 512 rows of the output block ----
    const float4 mean = smem[0][c];
    size_t op = base + (size_t)rg * ROWS_PER_THREAD * C4;
    #pragma unroll
    for (int i = 0; i < ROWS_PER_THREAD; i++) {
        o4[op + (size_t)i * C4] = mean;
    }
}

extern "C" void kernel_launch(void* const* d_in, const int* in_sizes, int n_in,
                              void* d_out, int out_size) {
    const float* x = (const float*)d_in[0];   // [4, 4096, 384] fp32
    float* out     = (float*)d_out;           // [4, 4096, 384] fp32
    (void)in_sizes; (void)n_in; (void)out_size;

    dim3 grid(C4 / CHUNK4 /*3*/, S / BLOCK /*8*/, 4 /*batch*/);
    dinopool_kernel<<<grid, NTHREADS>>>(x, out);
}